// round 11
// baseline (speedup 1.0000x reference)
#include <cuda_runtime.h>

#define LVLS 16
#define TSIZE 16384
#define NPTS 262144
#define TMASK 16383
#define PRIME1 (-1640531535)   // 2654435761 wrapped to int32
#define PRIME2 (805459861)
#define CTAS_PER_LVL 9
#define NTHREADS 1024
#define GTHREADS 960            // warps 0..29: gather
#define CTHREADS 64             // warps 30..31: transpose consumer
#define GRIDSZ (CTAS_PER_LVL * LVLS)   // 144 CTAs, 1/SM, single wave
#define NCHUNKS 16
#define CHPTS (NPTS / NCHUNKS)  // 16384 points per chunk
#define SLICE 1821              // ceil(CHPTS / 9) per gather CTA per chunk
#define TILEPTS 128             // consumer tile: 128 points x 16 levels
#define TILES_PER_CHUNK (CHPTS / TILEPTS)   // 128 (CTAs 0..127 own one each)
#define TPITCH 130              // float2 pitch of tile rows
#define GROUP 288               // counter arrivals per chunk: 144 prod + 144 cons

// Scratch in (L, N) layout of float2 — 33.5MB static device array (allowed).
__device__ float2 g_scr[(size_t)LVLS * NPTS];
// Per-chunk monotonic counters (never reset; targets derived from own arrival,
// so correct across correctness run, capture, and every replay).
__device__ unsigned int g_cnt[NCHUNKS];

// ---------------------------------------------------------------------------
// Warp-specialized fused kernel.
//  - Gather warps (960 thr): level table in smem, hash-grid gather, coalesced
//    float2 scratch stores; publish per-chunk completion.
//  - Consumer warps (64 thr): spin for chunk ready, transpose one 128-point
//    tile (L,N,2)->(N,L*2) via a private smem tile, overlapping the gather's
//    smem-bound compute with the transpose's L2/DRAM time.
// ---------------------------------------------------------------------------
__global__ __launch_bounds__(NTHREADS, 1)
void hash_enc_ws(const float* __restrict__ x,
                 const float* __restrict__ emb,
                 float* __restrict__ out)
{
    extern __shared__ float2 smem[];            // [0,TSIZE): table; then tile
    float2 (*tile)[TPITCH] = (float2 (*)[TPITCH])(smem + TSIZE);

    const int level = blockIdx.y;
    const int s     = blockIdx.x;                       // 0..8 slice in level
    const int bid   = blockIdx.y * CTAS_PER_LVL + blockIdx.x;   // 0..143
    const int tid   = threadIdx.x;

    if (tid < GTHREADS) {
        // ================= PRODUCER: gather =================
        {
            const float4* src = (const float4*)(emb + (size_t)level * TSIZE * 2);
            float4* dst = (float4*)smem;
            for (int i = tid; i < (TSIZE * 2) / 4; i += GTHREADS)
                dst[i] = src[i];
        }
        asm volatile("bar.sync 1, %0;" :: "n"(GTHREADS));

        // Per-level resolution (identical formula — index math unchanged)
        const float bgrow = expf((logf(512.0f) - logf(16.0f)) * (1.0f / 16.0f));
        const float scale = 16.0f * powf(bgrow, (float)level);
        float2* scr = g_scr + (size_t)level * NPTS;

        for (int c = 0; c < NCHUNKS; ++c) {
            const int cbase = c * CHPTS;
            const int start = cbase + s * SLICE;
            const int end   = min(start + SLICE, cbase + CHPTS);

            for (int n = start + tid; n < end; n += GTHREADS) {
                const float x0 = x[n * 3 + 0];
                const float x1 = x[n * 3 + 1];
                const float x2 = x[n * 3 + 2];

                const float u0 = x0 * scale, u1 = x1 * scale, u2 = x2 * scale;
                const float f0 = floorf(u0), f1 = floorf(u1), f2 = floorf(u2);
                const int   i0 = (int)f0,    i1 = (int)f1,    i2 = (int)f2;
                const float d0 = u0 - f0, d1 = u1 - f1, d2 = u2 - f2;
                const float o0 = 1.0f - d0, o1 = 1.0f - d1, o2 = 1.0f - d2;

                const int pl0 = i0;            const int ph0 = pl0 + 1;
                const int pl1 = i1 * PRIME1;   const int ph1 = pl1 + PRIME1;
                const int pl2 = i2 * PRIME2;   const int ph2 = pl2 + PRIME2;
                // frac==0 corners carry exactly-zero weight: hi = lo+1 safe.

                float ax = 0.0f, ay = 0.0f;
                #pragma unroll
                for (int k = 0; k < 8; ++k) {
                    const int a = (k >> 2) & 1;
                    const int b = (k >> 1) & 1;
                    const int cc = k & 1;
                    const int h = (a ? ph0 : pl0) ^ (b ? ph1 : pl1) ^ (cc ? ph2 : pl2);
                    const int idx = h & TMASK;
                    const float w = (a ? d0 : o0) * (b ? d1 : o1) * (cc ? d2 : o2);
                    const float2 v = smem[idx];
                    ax = fmaf(w, v.x, ax);
                    ay = fmaf(w, v.y, ay);
                }
                scr[n] = make_float2(ax, ay);   // coalesced 256B warp store
            }

            // Publish chunk slice: every thread fences, then one arrival.
            __threadfence();
            asm volatile("bar.sync 1, %0;" :: "n"(GTHREADS));
            if (tid == 0) atomicAdd(&g_cnt[c], 1u);
        }
    } else {
        // ================= CONSUMER: transpose =================
        const int ct = tid - GTHREADS;          // 0..63
        const int q  = ct & 7;                  // float4 slot in output row
        const int pr = ct >> 3;                 // 0..7
        const float4* scr4 = (const float4*)g_scr;
        float4* out4 = (float4*)out;

        for (int c = 0; c < NCHUNKS; ++c) {
            if (ct == 0) {
                const unsigned int old = atomicAdd(&g_cnt[c], 1u);
                const unsigned int target = (old / GROUP + 1u) * GROUP;
                for (;;) {
                    unsigned int v;
                    asm volatile("ld.acquire.gpu.u32 %0, [%1];"
                                 : "=r"(v) : "l"(&g_cnt[c]) : "memory");
                    if (v >= target) break;
                    __nanosleep(128);
                }
                __threadfence();                // acquire for the group
            }
            asm volatile("bar.sync 2, %0;" :: "n"(CTHREADS));

            if (bid < TILES_PER_CHUNK) {
                const int n0 = c * CHPTS + bid * TILEPTS;

                // Load: 16 x LDG.128 per thread (level l, slot ct), STS.128
                // contiguous per warp (conflict-free). __ldcg: L2-resident.
                #pragma unroll 8
                for (int l = 0; l < LVLS; ++l) {
                    const float4 v = __ldcg(scr4 + (size_t)l * (NPTS / 2)
                                            + (n0 >> 1) + ct);
                    *(float4*)&tile[l][2 * ct] = v;
                }
                asm volatile("bar.sync 2, %0;" :: "n"(CTHREADS));

                // Store: warp writes 4 consecutive 128B output rows per pass.
                #pragma unroll
                for (int i = 0; i < TILEPTS / 8; ++i) {
                    const int p = i * 8 + pr;
                    const float2 a = tile[2 * q][p];
                    const float2 b = tile[2 * q + 1][p];
                    out4[(size_t)(n0 + p) * (LVLS / 2) + q]
                        = make_float4(a.x, a.y, b.x, b.y);
                }
                asm volatile("bar.sync 2, %0;" :: "n"(CTHREADS));  // tile reuse
            }
        }
    }
}

extern "C" void kernel_launch(void* const* d_in, const int* in_sizes, int n_in,
                              void* d_out, int out_size)
{
    const float* x;
    const float* emb;
    if (in_sizes[0] == NPTS * 3) {
        x = (const float*)d_in[0];
        emb = (const float*)d_in[1];
    } else {
        x = (const float*)d_in[1];
        emb = (const float*)d_in[0];
    }
    float* out = (float*)d_out;

    const int smem_bytes = TSIZE * 2 * (int)sizeof(float)        // table 128KB
                         + LVLS * TPITCH * (int)sizeof(float2);  // tile ~16.6KB
    cudaFuncSetAttribute(hash_enc_ws,
                         cudaFuncAttributeMaxDynamicSharedMemorySize,
                         smem_bytes);

    dim3 grid(CTAS_PER_LVL, LVLS);   // 144 CTAs = one full wave @ 1 CTA/SM
    hash_enc_ws<<<grid, NTHREADS, smem_bytes>>>(x, emb, out);
}